// round 9
// baseline (speedup 1.0000x reference)
#include <cuda_runtime.h>
#include <cuda_fp16.h>
#include <cstdint>
#include <cstddef>

#define BB 4
#define NQ 16384
#define MP 4096
#define C1V 128
#define C2V 256
#define D0 256
#define D1 128
#define NTOT (BB*NQ)   // 65536

// ---------------- scratch (device globals; no allocation allowed) ----------------
__device__ float4 g_xyz2p[BB*MP];                  // packed xyz2 + norm (for merge/exact)
__device__ ulonglong2 g_xyz2d[BB*MP*2];            // dup-packed: (xx,yy),(zz,ww) per point
__device__ float  g_sc0[D0], g_sh0[D0], g_sc1[D1], g_sh1[D1];
__device__ float  g_wgt[NTOT*3];
__device__ int    g_idx[NTOT*3];
__device__ int    g_pi[(size_t)NTOT*12];           // 4 tiles x top-3 indices per query
__device__ __half g_A1h[(size_t)NTOT*C1V];         // points1 fp16 (16 MB)
__device__ __half g_A2h[BB*MP*C2V];                // points2 fp16 (8 MB)
__device__ __half g_W0a[256*256];                  // w0[0:256,:]^T  (K-major fp16)
__device__ __half g_W0b[256*128];                  // w0[256:384,:]^T (n=256 rows, k=128)
__device__ __half g_W1h[128*256];                  // w1^T (n=128 rows, k=256)
__device__ float  g_P2W[BB*MP*D0];                 // points2 @ w0a (16 MB, fp32)
__device__ __half g_G1h[(size_t)NTOT*D0];          // gathered first-layer partial fp16 (32 MB)
__device__ __half g_Hh[(size_t)NTOT*D0];           // layer-1 activations fp16 (32 MB)

// ---------------- PTX helpers ----------------
__device__ __forceinline__ uint32_t smem_u32(const void* p){
    uint32_t a;
    asm("{ .reg .u64 t; cvta.to.shared.u64 t, %1; cvt.u32.u64 %0, t; }" : "=r"(a) : "l"(p));
    return a;
}
__device__ __forceinline__ uint64_t pk(float a, float b){
    uint64_t r; asm("mov.b64 %0, {%1,%2};" : "=l"(r) : "f"(a), "f"(b)); return r;
}
__device__ __forceinline__ uint64_t fma2(uint64_t a, uint64_t b, uint64_t c){
    uint64_t r; asm("fma.rn.f32x2 %0, %1, %2, %3;" : "=l"(r) : "l"(a), "l"(b), "l"(c)); return r;
}
__device__ __forceinline__ void unpk(uint64_t v, float& lo, float& hi){
    asm("mov.b64 {%0,%1}, %2;" : "=f"(lo), "=f"(hi) : "l"(v));
}
__device__ __forceinline__ void cpa(uint32_t dst, const void* src){
    asm volatile("cp.async.ca.shared.global [%0], [%1], 16;" :: "r"(dst), "l"(src) : "memory");
}
__device__ __forceinline__ void cp_commit(){ asm volatile("cp.async.commit_group;" ::: "memory"); }
template<int NN> __device__ __forceinline__ void cp_wait(){ asm volatile("cp.async.wait_group %0;" :: "n"(NN) : "memory"); }

__device__ __forceinline__ void ldsm4(uint32_t& r0, uint32_t& r1, uint32_t& r2, uint32_t& r3, uint32_t addr){
    asm volatile("ldmatrix.sync.aligned.m8n8.x4.shared.b16 {%0,%1,%2,%3}, [%4];"
        : "=r"(r0), "=r"(r1), "=r"(r2), "=r"(r3) : "r"(addr));
}
__device__ __forceinline__ void mma16816(float* c, const uint32_t* a, const uint32_t* b){
    asm volatile(
        "mma.sync.aligned.m16n8k16.row.col.f32.f16.f16.f32 "
        "{%0,%1,%2,%3}, {%4,%5,%6,%7}, {%8,%9}, {%0,%1,%2,%3};"
        : "+f"(c[0]), "+f"(c[1]), "+f"(c[2]), "+f"(c[3])
        : "r"(a[0]), "r"(a[1]), "r"(a[2]), "r"(a[3]), "r"(b[0]), "r"(b[1]));
}

// ---------------- prep: pack xyz2 tables, BN scale/shift ----------------
__global__ void prep_kernel(const float* __restrict__ xyz2,
                            const float* __restrict__ G0, const float* __restrict__ B0,
                            const float* __restrict__ M0, const float* __restrict__ V0,
                            const float* __restrict__ G1, const float* __restrict__ B1,
                            const float* __restrict__ M1, const float* __restrict__ V1)
{
    int i = blockIdx.x*256 + threadIdx.x;
    if (i < BB*MP){
        float x = xyz2[i*3+0], y = xyz2[i*3+1], z = xyz2[i*3+2];
        float w = x*x + y*y + z*z;
        g_xyz2p[i] = make_float4(x, y, z, w);
        g_xyz2d[2*i+0] = make_ulonglong2(pk(x,x), pk(y,y));
        g_xyz2d[2*i+1] = make_ulonglong2(pk(z,z), pk(w,w));
    }
    if (blockIdx.x == 0){
        int t = threadIdx.x;
        if (t < D0){ float s = G0[t]*rsqrtf(V0[t]+1e-3f); g_sc0[t]=s; g_sh0[t]=B0[t]-M0[t]*s; }
        if (t < D1){ float s = G1[t]*rsqrtf(V1[t]+1e-3f); g_sc1[t]=s; g_sh1[t]=B1[t]-M1[t]*s; }
    }
}

// ---------------- fp32 -> fp16 vector convert ----------------
__global__ void __launch_bounds__(256) f2h_kernel(const float4* __restrict__ in, __half2* __restrict__ out){
    int i = blockIdx.x*256 + threadIdx.x;
    float4 v = in[i];
    out[2*i+0] = __floats2half2_rn(v.x, v.y);
    out[2*i+1] = __floats2half2_rn(v.z, v.w);
}

// ---------------- weight transpose + fp16 (K-major for B operand) ----------------
__global__ void __launch_bounds__(256) wtrans_kernel(const float* __restrict__ w0, const float* __restrict__ w1){
    int t = blockIdx.x*256 + threadIdx.x;            // 0..131071
    if (t < 65536){
        int n = t >> 8, k = t & 255;
        g_W0a[n*256 + k] = __float2half_rn(w0[k*256 + n]);
    } else if (t < 98304){
        int u = t - 65536; int n = u >> 7, k = u & 127;  // n<256, k<128
        g_W0b[n*128 + k] = __float2half_rn(w0[(256 + k)*256 + n]);
    } else {
        int u = t - 98304; int n = u >> 8, k = u & 255;  // n<128, k<256
        g_W1h[n*256 + k] = __float2half_rn(w1[k*128 + n]);
    }
}

// ------- 3-NN tile pass: 2 queries/thread, packed f32x2, divergent inserts -------
// grid = 1024 blocks: tile = blockIdx.x & 3, query-block (256 queries) = blockIdx.x >> 2.
__global__ void __launch_bounds__(128) nn3_kernel(const float* __restrict__ xyz1)
{
    __shared__ ulonglong2 s[2048];             // 1024 pts * 32 B = 32 KB
    const int tile = blockIdx.x & 3;
    const int q0 = (blockIdx.x >> 2)*256 + threadIdx.x*2;   // even; q0,q0+1 same batch
    const int b = q0 >> 14;

    const float xa = xyz1[q0*3+0], ya = xyz1[q0*3+1], za = xyz1[q0*3+2];
    const float xb = xyz1[q0*3+3], yb = xyz1[q0*3+4], zb = xyz1[q0*3+5];
    const uint64_t axx = pk(-2.f*xa, -2.f*xb);
    const uint64_t ayy = pk(-2.f*ya, -2.f*yb);
    const uint64_t azz = pk(-2.f*za, -2.f*zb);

    const ulonglong2* src = g_xyz2d + (size_t)(b*MP + tile*1024)*2;
    for (int i = threadIdx.x; i < 2048; i += 128) s[i] = src[i];
    __syncthreads();

    // shifted-space (d2 - n1) running top-3 per query
    float a0 = 3.0e37f, a1 = 3.0e37f, a2 = 3.0e37f; int ia0 = 0, ia1 = 0, ia2 = 0;
    float c0 = 3.0e37f, c1 = 3.0e37f, c2 = 3.0e37f; int ic0 = 0, ic1 = 0, ic2 = 0;

    #pragma unroll 4
    for (int m = 0; m < 1024; ++m){
        ulonglong2 A = s[2*m];
        ulonglong2 B = s[2*m+1];
        uint64_t d = fma2(azz, B.x, B.y);
        d = fma2(ayy, A.y, d);
        d = fma2(axx, A.x, d);
        float da, db; unpk(d, da, db);
        if (da < a2){
            if (da < a1){
                a2 = a1; ia2 = ia1;
                if (da < a0){ a1 = a0; ia1 = ia0; a0 = da; ia0 = m; }
                else        { a1 = da; ia1 = m; }
            } else { a2 = da; ia2 = m; }
        }
        if (db < c2){
            if (db < c1){
                c2 = c1; ic2 = ic1;
                if (db < c0){ c1 = c0; ic1 = ic0; c0 = db; ic0 = m; }
                else        { c1 = db; ic1 = m; }
            } else { c2 = db; ic2 = m; }
        }
    }

    const int base = tile*1024;
    int* oa = g_pi + ((size_t)q0*4 + tile)*3;
    oa[0] = base + ia0; oa[1] = base + ia1; oa[2] = base + ia2;
    int* ob = g_pi + ((size_t)(q0+1)*4 + tile)*3;
    ob[0] = base + ic0; ob[1] = base + ic1; ob[2] = base + ic2;
}

// ------- merge: exact-recompute distances of 12 candidates, exact top-3, weights -------
__global__ void __launch_bounds__(256) merge_kernel(const float* __restrict__ xyz1)
{
    const int q = blockIdx.x*256 + threadIdx.x;
    const int b = q >> 14;
    const float x = xyz1[q*3+0], y = xyz1[q*3+1], z = xyz1[q*3+2];
    const float n1 = x*x + y*y + z*z;
    const float ax = -2.f*x, ay = -2.f*y, az = -2.f*z;

    const int* pi = g_pi + (size_t)q*12;

    float b0v = 3.0e37f, b1v = 3.0e37f, b2v = 3.0e37f;
    int   i0 = 0, i1 = 0, i2 = 0;

    #pragma unroll
    for (int c = 0; c < 12; ++c){
        int gm = pi[c];
        float4 t = g_xyz2p[b*MP + gm];
        float d = fmaf(az, t.z, fmaf(ay, t.y, fmaf(ax, t.x, t.w)));
        if (d < b2v){
            if (d < b1v){
                b2v = b1v; i2 = i1;
                if (d < b0v){ b1v = b0v; i1 = i0; b0v = d; i0 = gm; }
                else        { b1v = d;   i1 = gm; }
            } else { b2v = d; i2 = gm; }
        }
    }

    float d0 = fmaxf(n1 + b0v, 1e-10f);
    float d1 = fmaxf(n1 + b1v, 1e-10f);
    float d2 = fmaxf(n1 + b2v, 1e-10f);
    float w0 = 1.f/d0, w1 = 1.f/d1, w2 = 1.f/d2;
    float inv = 1.f/(w0 + w1 + w2);
    g_wgt[q*3+0] = w0*inv; g_wgt[q*3+1] = w1*inv; g_wgt[q*3+2] = w2*inv;
    g_idx[q*3+0] = i0;     g_idx[q*3+1] = i1;     g_idx[q*3+2] = i2;
}

// ---------------- weighted gather of P2W rows -> fp16 first-layer partial ----------------
__global__ void __launch_bounds__(256) gather_kernel()
{
    int t = blockIdx.x*256 + threadIdx.x;
    int q = t >> 6;          // 64 threads per query (256 floats as float4)
    int c = t & 63;
    int b = q >> 14;
    float w0 = g_wgt[q*3+0], w1 = g_wgt[q*3+1], w2 = g_wgt[q*3+2];
    const float4* P = (const float4*)g_P2W;
    int base = b * (MP * (D0/4));
    float4 p0 = P[base + g_idx[q*3+0]*(D0/4) + c];
    float4 p1 = P[base + g_idx[q*3+1]*(D0/4) + c];
    float4 p2 = P[base + g_idx[q*3+2]*(D0/4) + c];
    float rx = w0*p0.x + w1*p1.x + w2*p2.x;
    float ry = w0*p0.y + w1*p1.y + w2*p2.y;
    float rz = w0*p0.z + w1*p1.z + w2*p2.z;
    float rw = w0*p0.w + w1*p1.w + w2*p2.w;
    __half2* o = (__half2*)g_G1h;
    o[((size_t)q*D0 >> 1) + c*2 + 0] = __floats2half2_rn(rx, ry);
    o[((size_t)q*D0 >> 1) + c*2 + 1] = __floats2half2_rn(rz, rw);
}

// ---------------- fp16 tensor-core GEMM: out = epi(A[M,K]h @ Bt[Nc,K]h^T (+G1h)) ------
// BM=128, BN=128, BK=32, 256 threads (8 warps: 4 along M x 2 along N), double-buffered.
template<bool GATHER, bool BN, bool OUT_HALF>
__global__ void __launch_bounds__(256) gemm_h(
    const __half* __restrict__ A, const __half* __restrict__ Bt,
    const float* __restrict__ scale, const float* __restrict__ shift,
    void* __restrict__ outv, int K, int NcOut)
{
    __shared__ __half As[2][128*40];
    __shared__ __half Bs[2][128*40];

    const int tid  = threadIdx.x;
    const int lane = tid & 31, warp = tid >> 5;
    const int wm = warp & 3, wn = warp >> 2;
    const int mBase = blockIdx.x * 128;
    const int nBase = blockIdx.y * 128;

    float acc[2][8][4];
    #pragma unroll
    for (int mt = 0; mt < 2; ++mt)
        #pragma unroll
        for (int nt = 0; nt < 8; ++nt)
            #pragma unroll
            for (int c = 0; c < 4; ++c) acc[mt][nt][c] = 0.f;

    const uint32_t sA_[2] = { smem_u32(As[0]), smem_u32(As[1]) };
    const uint32_t sB_[2] = { smem_u32(Bs[0]), smem_u32(Bs[1]) };

    const int g  = lane >> 3, lr = lane & 7;
    const uint32_t offA = (uint32_t)((wm*32 + (g&1)*8 + lr)*40 + (g>>1)*8);
    const uint32_t offB = (uint32_t)((wn*64 + (g>>1)*8 + lr)*40 + (g&1)*8);

    const int lrow = tid >> 1;                 // 0..127
    const int lseg2 = (tid & 1) * 2;           // 0 or 2
    const __half* Ag = A + (size_t)(mBase + lrow)*K + lseg2*8;
    const __half* Bg = Bt + (size_t)(nBase + lrow)*K + lseg2*8;
    const uint32_t dA = (uint32_t)(lrow*40 + lseg2*8)*2;
    const uint32_t dB = dA;

    auto load_tile = [&](int kc, int buf){
        const __half* a = Ag + kc*32;
        const __half* b = Bg + kc*32;
        cpa(sA_[buf] + dA,      a);
        cpa(sA_[buf] + dA + 16, a + 8);
        cpa(sB_[buf] + dB,      b);
        cpa(sB_[buf] + dB + 16, b + 8);
        cp_commit();
    };

    const int KC = K >> 5;
    load_tile(0, 0);
    for (int kc = 0; kc < KC; ++kc){
        const int buf = kc & 1;
        if (kc + 1 < KC){ load_tile(kc+1, buf^1); cp_wait<1>(); }
        else            { cp_wait<0>(); }
        __syncthreads();

        const uint32_t sA = sA_[buf], sB = sB_[buf];
        #pragma unroll
        for (int ks = 0; ks < 2; ++ks){
            uint32_t af[2][4];
            uint32_t bf[8][2];
            #pragma unroll
            for (int mt = 0; mt < 2; ++mt)
                ldsm4(af[mt][0], af[mt][1], af[mt][2], af[mt][3],
                      sA + (offA + mt*16*40 + ks*16)*2);
            #pragma unroll
            for (int ntp = 0; ntp < 4; ++ntp)
                ldsm4(bf[2*ntp][0], bf[2*ntp][1], bf[2*ntp+1][0], bf[2*ntp+1][1],
                      sB + (offB + ntp*16*40 + ks*16)*2);
            #pragma unroll
            for (int mt = 0; mt < 2; ++mt)
                #pragma unroll
                for (int nt = 0; nt < 8; ++nt)
                    mma16816(acc[mt][nt], af[mt], bf[nt]);
        }
        __syncthreads();
    }

    // ---------------- epilogue ----------------
    #pragma unroll
    for (int mt = 0; mt < 2; ++mt){
        #pragma unroll
        for (int h = 0; h < 2; ++h){
            const int r = mBase + wm*32 + mt*16 + (lane >> 2) + h*8;
            const __half* g1row = GATHER ? (g_G1h + (size_t)r*D0) : nullptr;
            #pragma unroll
            for (int nt = 0; nt < 8; ++nt){
                const int c = nBase + wn*64 + nt*8 + (lane & 3)*2;
                float v0 = acc[mt][nt][h*2+0];
                float v1 = acc[mt][nt][h*2+1];
                if (GATHER){
                    float2 gg = __half22float2(*(const __half2*)(g1row + c));
                    v0 += gg.x; v1 += gg.y;
                }
                if (BN){
                    float2 sc = *(const float2*)(scale + c);
                    float2 sh = *(const float2*)(shift + c);
                    v0 = fmaxf(fmaf(v0, sc.x, sh.x), 0.f);
                    v1 = fmaxf(fmaf(v1, sc.y, sh.y), 0.f);
                }
                if (OUT_HALF){
                    __half2* o = (__half2*)outv;
                    o[((size_t)r*NcOut + c) >> 1] = __floats2half2_rn(v0, v1);
                } else {
                    float2* o = (float2*)outv;
                    o[((size_t)r*NcOut + c) >> 1] = make_float2(v0, v1);
                }
            }
        }
    }
}

// ---------------- launch ----------------
extern "C" void kernel_launch(void* const* d_in, const int* in_sizes, int n_in,
                              void* d_out, int out_size)
{
    const float* xyz1    = (const float*)d_in[0];
    const float* xyz2    = (const float*)d_in[1];
    const float* points1 = (const float*)d_in[2];
    const float* points2 = (const float*)d_in[3];
    const float* w0 = (const float*)d_in[4];
    const float* g0 = (const float*)d_in[5];
    const float* b0 = (const float*)d_in[6];
    const float* m0 = (const float*)d_in[7];
    const float* v0 = (const float*)d_in[8];
    const float* w1 = (const float*)d_in[9];
    const float* g1 = (const float*)d_in[10];
    const float* b1 = (const float*)d_in[11];
    const float* m1 = (const float*)d_in[12];
    const float* v1 = (const float*)d_in[13];
    float* out = (float*)d_out;

    void *pA1h=nullptr, *pA2h=nullptr, *pW0a=nullptr, *pW0b=nullptr, *pW1h=nullptr,
         *pP2W=nullptr, *pHh=nullptr, *pSc0=nullptr, *pSh0=nullptr, *pSc1=nullptr, *pSh1=nullptr;
    cudaGetSymbolAddress(&pA1h, g_A1h);
    cudaGetSymbolAddress(&pA2h, g_A2h);
    cudaGetSymbolAddress(&pW0a, g_W0a);
    cudaGetSymbolAddress(&pW0b, g_W0b);
    cudaGetSymbolAddress(&pW1h, g_W1h);
    cudaGetSymbolAddress(&pP2W, g_P2W);
    cudaGetSymbolAddress(&pHh,  g_Hh);
    cudaGetSymbolAddress(&pSc0, g_sc0);
    cudaGetSymbolAddress(&pSh0, g_sh0);
    cudaGetSymbolAddress(&pSc1, g_sc1);
    cudaGetSymbolAddress(&pSh1, g_sh1);

    // 1) pack xyz2 tables + BN constants
    prep_kernel<<<64, 256>>>(xyz2, g0, b0, m0, v0, g1, b1, m1, v1);

    // 2-3) fp16 conversions of activations
    f2h_kernel<<<NTOT*C1V/4/256, 256>>>((const float4*)points1, (__half2*)pA1h);
    f2h_kernel<<<BB*MP*C2V/4/256, 256>>>((const float4*)points2, (__half2*)pA2h);

    // 4) 3-NN tile pass (profiled slot): 256 query-blocks x 4 point tiles
    nn3_kernel<<<1024, 128>>>(xyz1);

    // 5) exact merge -> weights + indices
    merge_kernel<<<256, 256>>>(xyz1);

    // 6) weight transpose + fp16
    wtrans_kernel<<<512, 256>>>(w0, w1);

    // 7) P2W = points2 @ w0[0:256,:]   (M=16384, K=256, N=256) -> fp32
    gemm_h<false,false,false><<<dim3(128, 2), 256>>>(
        (const __half*)pA2h, (const __half*)pW0a, nullptr, nullptr, pP2W, 256, 256);

    // 8) G1h = weighted gather of P2W rows (= interp @ w0[0:256,:]) -> fp16
    gather_kernel<<<16384, 256>>>();

    // 9) H = relu(bn0(points1 @ w0[256:384,:] + G1h)) -> fp16  (M=65536, K=128, N=256)
    gemm_h<true,true,true><<<dim3(512, 2), 256>>>(
        (const __half*)pA1h, (const __half*)pW0b,
        (const float*)pSc0, (const float*)pSh0, pHh, 128, 256);

    // 10) out = relu(bn1(H @ w1)) -> fp32   (M=65536, K=256, N=128)
    gemm_h<false,true,false><<<dim3(512, 1), 256>>>(
        (const __half*)pHh, (const __half*)pW1h,
        (const float*)pSc1, (const float*)pSh1, out, 256, 128);
}

// round 10
// speedup vs baseline: 1.1142x; 1.1142x over previous
#include <cuda_runtime.h>
#include <cuda_fp16.h>
#include <cstdint>
#include <cstddef>

#define BB 4
#define NQ 16384
#define MP 4096
#define C1V 128
#define C2V 256
#define D0 256
#define D1 128
#define NTOT (BB*NQ)   // 65536

// ---------------- scratch (device globals; no allocation allowed) ----------------
__device__ float4 g_xyz2p[BB*MP];                  // packed xyz2 + norm
__device__ float  g_sc0[D0], g_sh0[D0], g_sc1[D1], g_sh1[D1];
__device__ float  g_wgt[NTOT*3];
__device__ int    g_idx[NTOT*3];
__device__ int    g_pi[(size_t)NTOT*12];           // 4 tiles x top-3 indices per query
__device__ __half g_A1h[(size_t)NTOT*C1V];         // points1 fp16 (16 MB)
__device__ __half g_A2h[BB*MP*C2V];                // points2 fp16 (8 MB)
__device__ __half g_W0a[256*256];                  // w0[0:256,:]^T  (K-major fp16)
__device__ __half g_W0b[256*128];                  // w0[256:384,:]^T (n=256 rows, k=128)
__device__ __half g_W1h[128*256];                  // w1^T (n=128 rows, k=256)
__device__ float  g_P2W[BB*MP*D0];                 // points2 @ w0a (16 MB, fp32)
__device__ __half g_G1h[(size_t)NTOT*D0];          // gathered first-layer partial fp16 (32 MB)
__device__ __half g_Hh[(size_t)NTOT*D0];           // layer-1 activations fp16 (32 MB)

// ---------------- PTX helpers ----------------
__device__ __forceinline__ uint32_t smem_u32(const void* p){
    uint32_t a;
    asm("{ .reg .u64 t; cvta.to.shared.u64 t, %1; cvt.u32.u64 %0, t; }" : "=r"(a) : "l"(p));
    return a;
}
__device__ __forceinline__ void cpa(uint32_t dst, const void* src){
    asm volatile("cp.async.ca.shared.global [%0], [%1], 16;" :: "r"(dst), "l"(src) : "memory");
}
__device__ __forceinline__ void cp_commit(){ asm volatile("cp.async.commit_group;" ::: "memory"); }
template<int NN> __device__ __forceinline__ void cp_wait(){ asm volatile("cp.async.wait_group %0;" :: "n"(NN) : "memory"); }

__device__ __forceinline__ void ldsm4(uint32_t& r0, uint32_t& r1, uint32_t& r2, uint32_t& r3, uint32_t addr){
    asm volatile("ldmatrix.sync.aligned.m8n8.x4.shared.b16 {%0,%1,%2,%3}, [%4];"
        : "=r"(r0), "=r"(r1), "=r"(r2), "=r"(r3) : "r"(addr));
}
__device__ __forceinline__ void mma16816(float* c, const uint32_t* a, const uint32_t* b){
    asm volatile(
        "mma.sync.aligned.m16n8k16.row.col.f32.f16.f16.f32 "
        "{%0,%1,%2,%3}, {%4,%5,%6,%7}, {%8,%9}, {%0,%1,%2,%3};"
        : "+f"(c[0]), "+f"(c[1]), "+f"(c[2]), "+f"(c[3])
        : "r"(a[0]), "r"(a[1]), "r"(a[2]), "r"(a[3]), "r"(b[0]), "r"(b[1]));
}

// ---------------- prep: pack xyz2 (+norm), BN scale/shift ----------------
__global__ void prep_kernel(const float* __restrict__ xyz2,
                            const float* __restrict__ G0, const float* __restrict__ B0,
                            const float* __restrict__ M0, const float* __restrict__ V0,
                            const float* __restrict__ G1, const float* __restrict__ B1,
                            const float* __restrict__ M1, const float* __restrict__ V1)
{
    int i = blockIdx.x*256 + threadIdx.x;
    if (i < BB*MP){
        float x = xyz2[i*3+0], y = xyz2[i*3+1], z = xyz2[i*3+2];
        g_xyz2p[i] = make_float4(x, y, z, x*x + y*y + z*z);
    }
    if (blockIdx.x == 0){
        int t = threadIdx.x;
        if (t < D0){ float s = G0[t]*rsqrtf(V0[t]+1e-3f); g_sc0[t]=s; g_sh0[t]=B0[t]-M0[t]*s; }
        if (t < D1){ float s = G1[t]*rsqrtf(V1[t]+1e-3f); g_sc1[t]=s; g_sh1[t]=B1[t]-M1[t]*s; }
    }
}

// ---------------- fp32 -> fp16 vector convert ----------------
__global__ void __launch_bounds__(256) f2h_kernel(const float4* __restrict__ in, __half2* __restrict__ out){
    int i = blockIdx.x*256 + threadIdx.x;
    float4 v = in[i];
    out[2*i+0] = __floats2half2_rn(v.x, v.y);
    out[2*i+1] = __floats2half2_rn(v.z, v.w);
}

// ---------------- weight transpose + fp16 (K-major for B operand) ----------------
__global__ void __launch_bounds__(256) wtrans_kernel(const float* __restrict__ w0, const float* __restrict__ w1){
    int t = blockIdx.x*256 + threadIdx.x;            // 0..131071
    if (t < 65536){
        int n = t >> 8, k = t & 255;
        g_W0a[n*256 + k] = __float2half_rn(w0[k*256 + n]);
    } else if (t < 98304){
        int u = t - 65536; int n = u >> 7, k = u & 127;  // n<256, k<128
        g_W0b[n*128 + k] = __float2half_rn(w0[(256 + k)*256 + n]);
    } else {
        int u = t - 98304; int n = u >> 8, k = u & 255;  // n<128, k<256
        g_W1h[n*256 + k] = __float2half_rn(w1[k*128 + n]);
    }
}

// ---------------- 3-NN tile pass: scalar loop, 256 queries/block ----------------
// grid = 1024 blocks: tile = blockIdx.x & 3, query-block (256 queries) = blockIdx.x >> 2.
__global__ void __launch_bounds__(256) nn3_kernel(const float* __restrict__ xyz1)
{
    __shared__ float4 s[1024];                 // 16 KB
    const int tile = blockIdx.x & 3;
    const int q = (blockIdx.x >> 2)*256 + threadIdx.x;
    const int b = q >> 14;
    const float x = xyz1[q*3+0], y = xyz1[q*3+1], z = xyz1[q*3+2];
    const float ax = -2.f*x, ay = -2.f*y, az = -2.f*z;

    const float4* src = g_xyz2p + b*MP + tile*1024;
    for (int m = threadIdx.x; m < 1024; m += 256) s[m] = src[m];
    __syncthreads();

    float b0v = 3.0e37f, b1v = 3.0e37f, b2v = 3.0e37f;   // shifted space (d2 - n1)
    int   i0 = 0, i1 = 0, i2 = 0;

    #pragma unroll 4
    for (int m = 0; m < 1024; ++m){
        float4 t = s[m];
        float d = fmaf(az, t.z, fmaf(ay, t.y, fmaf(ax, t.x, t.w)));
        if (d < b2v){
            if (d < b1v){
                b2v = b1v; i2 = i1;
                if (d < b0v){ b1v = b0v; i1 = i0; b0v = d; i0 = m; }
                else        { b1v = d;   i1 = m; }
            } else { b2v = d; i2 = m; }
        }
    }

    const int base = tile*1024;
    int* o = g_pi + ((size_t)q*4 + tile)*3;
    o[0] = base + i0; o[1] = base + i1; o[2] = base + i2;
}

// ------- merge: exact-recompute distances of 12 candidates, exact top-3, weights -------
__global__ void __launch_bounds__(256) merge_kernel(const float* __restrict__ xyz1)
{
    const int q = blockIdx.x*256 + threadIdx.x;
    const int b = q >> 14;
    const float x = xyz1[q*3+0], y = xyz1[q*3+1], z = xyz1[q*3+2];
    const float n1 = x*x + y*y + z*z;
    const float ax = -2.f*x, ay = -2.f*y, az = -2.f*z;

    const int* pi = g_pi + (size_t)q*12;

    float b0v = 3.0e37f, b1v = 3.0e37f, b2v = 3.0e37f;
    int   i0 = 0, i1 = 0, i2 = 0;

    // tiles in index order; within tile candidates distance-sorted with earliest-index
    // tie-keeping; strict-< insertion reproduces top_k's lowest-index tie-break.
    #pragma unroll
    for (int c = 0; c < 12; ++c){
        int gm = pi[c];
        float4 t = g_xyz2p[b*MP + gm];
        float d = fmaf(az, t.z, fmaf(ay, t.y, fmaf(ax, t.x, t.w)));
        if (d < b2v){
            if (d < b1v){
                b2v = b1v; i2 = i1;
                if (d < b0v){ b1v = b0v; i1 = i0; b0v = d; i0 = gm; }
                else        { b1v = d;   i1 = gm; }
            } else { b2v = d; i2 = gm; }
        }
    }

    float d0 = fmaxf(n1 + b0v, 1e-10f);
    float d1 = fmaxf(n1 + b1v, 1e-10f);
    float d2 = fmaxf(n1 + b2v, 1e-10f);
    float w0 = 1.f/d0, w1 = 1.f/d1, w2 = 1.f/d2;
    float inv = 1.f/(w0 + w1 + w2);
    g_wgt[q*3+0] = w0*inv; g_wgt[q*3+1] = w1*inv; g_wgt[q*3+2] = w2*inv;
    g_idx[q*3+0] = i0;     g_idx[q*3+1] = i1;     g_idx[q*3+2] = i2;
}

// ---------------- weighted gather of P2W rows -> fp16 first-layer partial ----------------
__global__ void __launch_bounds__(256) gather_kernel()
{
    int t = blockIdx.x*256 + threadIdx.x;
    int q = t >> 6;          // 64 threads per query (256 floats as float4)
    int c = t & 63;
    int b = q >> 14;
    float w0 = g_wgt[q*3+0], w1 = g_wgt[q*3+1], w2 = g_wgt[q*3+2];
    const float4* P = (const float4*)g_P2W;
    int base = b * (MP * (D0/4));
    float4 p0 = P[base + g_idx[q*3+0]*(D0/4) + c];
    float4 p1 = P[base + g_idx[q*3+1]*(D0/4) + c];
    float4 p2 = P[base + g_idx[q*3+2]*(D0/4) + c];
    float rx = w0*p0.x + w1*p1.x + w2*p2.x;
    float ry = w0*p0.y + w1*p1.y + w2*p2.y;
    float rz = w0*p0.z + w1*p1.z + w2*p2.z;
    float rw = w0*p0.w + w1*p1.w + w2*p2.w;
    __half2* o = (__half2*)g_G1h;
    o[((size_t)q*D0 >> 1) + c*2 + 0] = __floats2half2_rn(rx, ry);
    o[((size_t)q*D0 >> 1) + c*2 + 1] = __floats2half2_rn(rz, rw);
}

// ---------------- fp16 tensor-core GEMM: out = epi(A[M,K]h @ Bt[Nc,K]h^T (+G1h)) ------
// BM=128, BN=128, BK=32, 256 threads (8 warps: 4 along M x 2 along N), double-buffered.
template<bool GATHER, bool BN, bool OUT_HALF>
__global__ void __launch_bounds__(256) gemm_h(
    const __half* __restrict__ A, const __half* __restrict__ Bt,
    const float* __restrict__ scale, const float* __restrict__ shift,
    void* __restrict__ outv, int K, int NcOut)
{
    __shared__ __half As[2][128*40];
    __shared__ __half Bs[2][128*40];

    const int tid  = threadIdx.x;
    const int lane = tid & 31, warp = tid >> 5;
    const int wm = warp & 3, wn = warp >> 2;
    const int mBase = blockIdx.x * 128;
    const int nBase = blockIdx.y * 128;

    float acc[2][8][4];
    #pragma unroll
    for (int mt = 0; mt < 2; ++mt)
        #pragma unroll
        for (int nt = 0; nt < 8; ++nt)
            #pragma unroll
            for (int c = 0; c < 4; ++c) acc[mt][nt][c] = 0.f;

    const uint32_t sA_[2] = { smem_u32(As[0]), smem_u32(As[1]) };
    const uint32_t sB_[2] = { smem_u32(Bs[0]), smem_u32(Bs[1]) };

    const int g  = lane >> 3, lr = lane & 7;
    const uint32_t offA = (uint32_t)((wm*32 + (g&1)*8 + lr)*40 + (g>>1)*8);
    const uint32_t offB = (uint32_t)((wn*64 + (g>>1)*8 + lr)*40 + (g&1)*8);

    const int lrow = tid >> 1;                 // 0..127
    const int lseg2 = (tid & 1) * 2;           // 0 or 2
    const __half* Ag = A + (size_t)(mBase + lrow)*K + lseg2*8;
    const __half* Bg = Bt + (size_t)(nBase + lrow)*K + lseg2*8;
    const uint32_t dA = (uint32_t)(lrow*40 + lseg2*8)*2;
    const uint32_t dB = dA;

    auto load_tile = [&](int kc, int buf){
        const __half* a = Ag + kc*32;
        const __half* b = Bg + kc*32;
        cpa(sA_[buf] + dA,      a);
        cpa(sA_[buf] + dA + 16, a + 8);
        cpa(sB_[buf] + dB,      b);
        cpa(sB_[buf] + dB + 16, b + 8);
        cp_commit();
    };

    const int KC = K >> 5;
    load_tile(0, 0);
    for (int kc = 0; kc < KC; ++kc){
        const int buf = kc & 1;
        if (kc + 1 < KC){ load_tile(kc+1, buf^1); cp_wait<1>(); }
        else            { cp_wait<0>(); }
        __syncthreads();

        const uint32_t sA = sA_[buf], sB = sB_[buf];
        #pragma unroll
        for (int ks = 0; ks < 2; ++ks){
            uint32_t af[2][4];
            uint32_t bf[8][2];
            #pragma unroll
            for (int mt = 0; mt < 2; ++mt)
                ldsm4(af[mt][0], af[mt][1], af[mt][2], af[mt][3],
                      sA + (offA + mt*16*40 + ks*16)*2);
            #pragma unroll
            for (int ntp = 0; ntp < 4; ++ntp)
                ldsm4(bf[2*ntp][0], bf[2*ntp][1], bf[2*ntp+1][0], bf[2*ntp+1][1],
                      sB + (offB + ntp*16*40 + ks*16)*2);
            #pragma unroll
            for (int mt = 0; mt < 2; ++mt)
                #pragma unroll
                for (int nt = 0; nt < 8; ++nt)
                    mma16816(acc[mt][nt], af[mt], bf[nt]);
        }
        __syncthreads();
    }

    // ---------------- epilogue ----------------
    #pragma unroll
    for (int mt = 0; mt < 2; ++mt){
        #pragma unroll
        for (int h = 0; h < 2; ++h){
            const int r = mBase + wm*32 + mt*16 + (lane >> 2) + h*8;
            const __half* g1row = GATHER ? (g_G1h + (size_t)r*D0) : nullptr;
            #pragma unroll
            for (int nt = 0; nt < 8; ++nt){
                const int c = nBase + wn*64 + nt*8 + (lane & 3)*2;
                float v0 = acc[mt][nt][h*2+0];
                float v1 = acc[mt][nt][h*2+1];
                if (GATHER){
                    float2 gg = __half22float2(*(const __half2*)(g1row + c));
                    v0 += gg.x; v1 += gg.y;
                }
                if (BN){
                    float2 sc = *(const float2*)(scale + c);
                    float2 sh = *(const float2*)(shift + c);
                    v0 = fmaxf(fmaf(v0, sc.x, sh.x), 0.f);
                    v1 = fmaxf(fmaf(v1, sc.y, sh.y), 0.f);
                }
                if (OUT_HALF){
                    __half2* o = (__half2*)outv;
                    o[((size_t)r*NcOut + c) >> 1] = __floats2half2_rn(v0, v1);
                } else {
                    float2* o = (float2*)outv;
                    o[((size_t)r*NcOut + c) >> 1] = make_float2(v0, v1);
                }
            }
        }
    }
}

// ---------------- launch ----------------
extern "C" void kernel_launch(void* const* d_in, const int* in_sizes, int n_in,
                              void* d_out, int out_size)
{
    const float* xyz1    = (const float*)d_in[0];
    const float* xyz2    = (const float*)d_in[1];
    const float* points1 = (const float*)d_in[2];
    const float* points2 = (const float*)d_in[3];
    const float* w0 = (const float*)d_in[4];
    const float* g0 = (const float*)d_in[5];
    const float* b0 = (const float*)d_in[6];
    const float* m0 = (const float*)d_in[7];
    const float* v0 = (const float*)d_in[8];
    const float* w1 = (const float*)d_in[9];
    const float* g1 = (const float*)d_in[10];
    const float* b1 = (const float*)d_in[11];
    const float* m1 = (const float*)d_in[12];
    const float* v1 = (const float*)d_in[13];
    float* out = (float*)d_out;

    void *pA1h=nullptr, *pA2h=nullptr, *pW0a=nullptr, *pW0b=nullptr, *pW1h=nullptr,
         *pP2W=nullptr, *pHh=nullptr, *pSc0=nullptr, *pSh0=nullptr, *pSc1=nullptr, *pSh1=nullptr;
    cudaGetSymbolAddress(&pA1h, g_A1h);
    cudaGetSymbolAddress(&pA2h, g_A2h);
    cudaGetSymbolAddress(&pW0a, g_W0a);
    cudaGetSymbolAddress(&pW0b, g_W0b);
    cudaGetSymbolAddress(&pW1h, g_W1h);
    cudaGetSymbolAddress(&pP2W, g_P2W);
    cudaGetSymbolAddress(&pHh,  g_Hh);
    cudaGetSymbolAddress(&pSc0, g_sc0);
    cudaGetSymbolAddress(&pSh0, g_sh0);
    cudaGetSymbolAddress(&pSc1, g_sc1);
    cudaGetSymbolAddress(&pSh1, g_sh1);

    // 1) pack xyz2 + BN constants
    prep_kernel<<<64, 256>>>(xyz2, g0, b0, m0, v0, g1, b1, m1, v1);

    // 2-3) fp16 conversions of activations
    f2h_kernel<<<NTOT*C1V/4/256, 256>>>((const float4*)points1, (__half2*)pA1h);
    f2h_kernel<<<BB*MP*C2V/4/256, 256>>>((const float4*)points2, (__half2*)pA2h);

    // 4) 3-NN tile pass (profiled slot): 256 query-blocks x 4 point tiles, 256 thr/blk
    nn3_kernel<<<1024, 256>>>(xyz1);

    // 5) exact merge -> weights + indices
    merge_kernel<<<256, 256>>>(xyz1);

    // 6) weight transpose + fp16
    wtrans_kernel<<<512, 256>>>(w0, w1);

    // 7) P2W = points2 @ w0[0:256,:]   (M=16384, K=256, N=256) -> fp32
    gemm_h<false,false,false><<<dim3(128, 2), 256>>>(
        (const __half*)pA2h, (const __half*)pW0a, nullptr, nullptr, pP2W, 256, 256);

    // 8) G1h = weighted gather of P2W rows (= interp @ w0[0:256,:]) -> fp16
    gather_kernel<<<16384, 256>>>();

    // 9) H = relu(bn0(points1 @ w0[256:384,:] + G1h)) -> fp16  (M=65536, K=128, N=256)
    gemm_h<true,true,true><<<dim3(512, 2), 256>>>(
        (const __half*)pA1h, (const __half*)pW0b,
        (const float*)pSc0, (const float*)pSh0, pHh, 128, 256);

    // 10) out = relu(bn1(H @ w1)) -> fp32   (M=65536, K=256, N=128)
    gemm_h<false,true,false><<<dim3(512, 1), 256>>>(
        (const __half*)pHh, (const __half*)pW1h,
        (const float*)pSc1, (const float*)pSh1, out, 256, 128);
}